// round 10
// baseline (speedup 1.0000x reference)
#include <cuda_runtime.h>
#include <cuda_fp16.h>

// GCN link predictor, CSR gather formulation with PRESCALED fp16 rows:
//   norm[e] = dinv[s]*dinv[d] factorized:  agg[d] = dinv[d] * sum( h[s]*dinv[s] )
//   -> fp16 gather rows store h*dinv (prescaled); CSR payload = src only (4B).
//   h1 = x @ W1;  a1 = relu( dinv*sum(h1h[src]) + h1*dinv^2 + b1 )
//   h2 = a1 @ W2; a2h = fp16( dinv*sum(h2h[src]) + h2*dinv^2 + b2 )
//   logits[e] = dot(a2h[src], a2h[dst]) in fp32
//
// Launches: init -> convert -> lookback-scan -> [csr_fill | gemm1] ->
//           gather1 -> gemm2 -> gather2 -> logits
//
// NOTE: __device__ scratch arrays are ONLY referenced inside device code
// (host-side use of the symbol is UB and silently corrupts via ATS on GB300).

#define N_NODES 100000
#define MAX_E   1600000
#define D_IN    32
#define D_HID   64
#define D_OUT   32

#define LBCH    1024                              // elements per scan chunk
#define NLB     ((N_NODES + LBCH - 1) / LBCH)     // 98 chunks

__device__ __align__(16) int    g_cnt [N_NODES];
__device__ __align__(16) int    g_off [N_NODES];
__device__ __align__(16) float  g_dinv[N_NODES];
__device__ __align__(16) float  g_h1  [N_NODES * D_HID];
__device__ __align__(16) __half g_h1h [N_NODES * D_HID];   // prescaled h1*dinv
__device__ __align__(16) float  g_a1  [N_NODES * D_HID];
__device__ __align__(16) float  g_h2  [N_NODES * D_OUT];
__device__ __align__(16) __half g_h2h [N_NODES * D_OUT];   // prescaled h2*dinv
__device__ __align__(16) __half g_a2h [N_NODES * D_OUT];
__device__ __align__(16) int    g_src [MAX_E];
__device__ __align__(16) int    g_dst [MAX_E];
__device__ __align__(16) int    g_pos [MAX_E];
__device__ __align__(16) int    g_csr [MAX_E];    // src index only
__device__ unsigned long long   g_lb  [NLB];      // lookback: val<<2 | flag
__device__ unsigned int         g_ticket;
__device__ int                  g_is64;

// ---------------------------------------------------------------------------
// 0) init: zero counts + scan state + dtype detect
// ---------------------------------------------------------------------------
__global__ void k_init(const void* __restrict__ ei, int n) {
    int i = blockIdx.x * blockDim.x + threadIdx.x;
    if (i < n) g_cnt[i] = 0;
    if (i < NLB) g_lb[i] = 0ull;
    if (i == 0) {
        g_ticket = 0u;
        const long long* p = (const long long*)ei;
        int is64 = 1;
        #pragma unroll
        for (int k = 0; k < 8; k++) {
            long long v = p[k];
            if (v < 0 || v >= N_NODES) is64 = 0;
        }
        g_is64 = is64;
    }
}

// ---------------------------------------------------------------------------
// 1) convert indices + degree histogram (records per-edge slot)
// ---------------------------------------------------------------------------
__global__ void k_convert(const void* __restrict__ ei, int E) {
    int i = blockIdx.x * blockDim.x + threadIdx.x;
    if (i >= 2 * E) return;
    int v;
    if (g_is64) v = (int)((const long long*)ei)[i];
    else        v = ((const int*)ei)[i];
    v = min(max(v, 0), N_NODES - 1);
    if (i < E) {
        g_src[i] = v;
    } else {
        int e = i - E;
        g_dst[e] = v;
        g_pos[e] = atomicAdd(&g_cnt[v], 1);
    }
}

// ---------------------------------------------------------------------------
// 2) single-launch decoupled-lookback exclusive scan (+ fused dinv)
// ---------------------------------------------------------------------------
__global__ void k_scan(int n) {     // grid = NLB, block = 256
    __shared__ int sh[256];
    __shared__ int s_bid;
    __shared__ int s_excl;
    int t = threadIdx.x;
    if (t == 0) s_bid = (int)atomicAdd(&g_ticket, 1u);
    __syncthreads();
    int bid  = s_bid;
    int base = bid * LBCH + t * 4;

    int4 c4 = make_int4(0, 0, 0, 0);
    if (base + 3 < n) {
        c4 = *reinterpret_cast<const int4*>(g_cnt + base);
    } else {
        int* cp = (int*)&c4;
        #pragma unroll
        for (int k = 0; k < 4; k++) cp[k] = (base + k < n) ? g_cnt[base + k] : 0;
    }
    int lsum = c4.x + c4.y + c4.z + c4.w;
    sh[t] = lsum;
    __syncthreads();
    #pragma unroll
    for (int d = 1; d < 256; d <<= 1) {
        int v = (t >= d) ? sh[t - d] : 0;
        __syncthreads();
        sh[t] += v;
        __syncthreads();
    }
    int total = sh[255];
    int texcl = sh[t] - lsum;

    if (t == 0) {
        atomicExch(&g_lb[bid], ((unsigned long long)total << 2) | 1ull);
        long long excl = 0;
        int j = bid - 1;
        while (j >= 0) {
            unsigned long long v;
            do { v = atomicAdd(&g_lb[j], 0ull); } while ((v & 3ull) == 0ull);
            excl += (long long)(v >> 2);
            if ((v & 3ull) == 2ull) break;
            j--;
        }
        atomicExch(&g_lb[bid],
                   ((unsigned long long)(excl + total) << 2) | 2ull);
        s_excl = (int)excl;
    }
    __syncthreads();
    int run = s_excl + texcl;

    int off[4];
    off[0] = run;
    off[1] = off[0] + c4.x;
    off[2] = off[1] + c4.y;
    off[3] = off[2] + c4.z;
    if (base + 3 < n) {
        *reinterpret_cast<int4*>(g_off + base) = *reinterpret_cast<int4*>(off);
        float4 dv = make_float4(rsqrtf((float)(c4.x + 1)), rsqrtf((float)(c4.y + 1)),
                                rsqrtf((float)(c4.z + 1)), rsqrtf((float)(c4.w + 1)));
        *reinterpret_cast<float4*>(g_dinv + base) = dv;
    } else {
        int* cp = (int*)&c4;
        #pragma unroll
        for (int k = 0; k < 4; k++) if (base + k < n) {
            g_off[base + k]  = off[k];
            g_dinv[base + k] = rsqrtf((float)(cp[k] + 1));
        }
    }
}

// ---------------------------------------------------------------------------
// 3) FUSED: CSR fill (src-only payload)  ||  GEMM1 with dinv prescale
//    blocks [0, fb) fill; blocks [fb, fb+gb) gemm1
// ---------------------------------------------------------------------------
__global__ void k_fill_gemm1(int E, const float* __restrict__ x,
                             const float* __restrict__ W1, int n, int fb) {
    __shared__ float sW[D_IN * D_HID];
    __shared__ float sx[4 * D_IN];
    int tid = threadIdx.x;

    if ((int)blockIdx.x < fb) {
        int e = blockIdx.x * blockDim.x + tid;
        if (e >= E) return;
        int s = g_src[e];
        int d = g_dst[e];
        g_csr[g_off[d] + g_pos[e]] = s;
        return;
    }

    // gemm1: h1 = x @ W1 (fp32) ; h1h = fp16(h1 * dinv)
    int bid = blockIdx.x - fb;
    for (int i = tid; i < D_IN * D_HID; i += 256) sW[i] = W1[i];
    int node0 = bid * 4;
    if (tid < 4 * D_IN) {
        int nn = node0 + tid / D_IN;
        sx[tid] = (nn < n) ? x[nn * D_IN + (tid % D_IN)] : 0.0f;
    }
    __syncthreads();
    int local = tid >> 6;
    int j     = tid & 63;
    int node  = node0 + local;
    if (node < n) {
        float acc = 0.0f;
        #pragma unroll
        for (int k = 0; k < D_IN; k++)
            acc = fmaf(sx[local * D_IN + k], sW[k * D_HID + j], acc);
        g_h1 [node * D_HID + j] = acc;
        g_h1h[node * D_HID + j] = __float2half(acc * g_dinv[node]);
    }
}

// ---------------------------------------------------------------------------
// fp16 sum helpers (no weight — rows are prescaled)
// ---------------------------------------------------------------------------
__device__ __forceinline__ void sum_row8(float* acc, uint4 r) {
    __half2* h = reinterpret_cast<__half2*>(&r);
    #pragma unroll
    for (int k = 0; k < 4; k++) {
        float2 f = __half22float2(h[k]);
        acc[2 * k + 0] += f.x;
        acc[2 * k + 1] += f.y;
    }
}

__device__ __forceinline__ void sum_row4(float* acc, uint2 r) {
    __half2* h = reinterpret_cast<__half2*>(&r);
    #pragma unroll
    for (int k = 0; k < 2; k++) {
        float2 f = __half22float2(h[k]);
        acc[2 * k + 0] += f.x;
        acc[2 * k + 1] += f.y;
    }
}

// ---------------------------------------------------------------------------
// 4) gather layer 1: 8 threads/node, 8 cols each; 8-edge batches,
//    4B csr entries, two-phase (shuffles -> 8 loads -> sums)
// ---------------------------------------------------------------------------
__global__ void k_gather1(const float* __restrict__ b1, int n) {
    int lane = threadIdx.x & 31;
    int t    = lane & 7;
    int node = blockIdx.x * 32 + (threadIdx.x >> 3);
    if (node >= n) return;
    unsigned gmask = 0xFFu << (lane & 24);
    int beg = g_off[node];
    int end = beg + g_cnt[node];
    const uint4* rows = reinterpret_cast<const uint4*>(g_h1h);  // 8 uint4 / row
    float acc[8];
    #pragma unroll
    for (int k = 0; k < 8; k++) acc[k] = 0.0f;
    int nfull = (end - beg) & ~7;
    int i = beg;
    for (; i < beg + nfull; i += 8) {
        int e = g_csr[i + t];
        int ex[8];
        #pragma unroll
        for (int k = 0; k < 8; k++) ex[k] = __shfl_sync(gmask, e, k, 8);
        uint4 r[8];
        #pragma unroll
        for (int k = 0; k < 8; k++) r[k] = rows[ex[k] * 8 + t];
        #pragma unroll
        for (int k = 0; k < 8; k++) sum_row8(acc, r[k]);
    }
    if (i < end) {
        int e = (i + t < end) ? g_csr[i + t] : 0;
        int rem = end - i;
        #pragma unroll
        for (int k = 0; k < 8; k++) {
            if (k >= rem) break;
            int ex = __shfl_sync(gmask, e, k, 8);
            sum_row8(acc, rows[ex * 8 + t]);
        }
    }
    float di = g_dinv[node];
    float d2 = di * di;
    const float* selfp = g_h1 + node * D_HID + t * 8;
    const float* bp    = b1 + t * 8;
    float* outp        = g_a1 + node * D_HID + t * 8;
    #pragma unroll
    for (int half = 0; half < 2; half++) {
        float4 s4 = *reinterpret_cast<const float4*>(selfp + half * 4);
        float4 b4 = *reinterpret_cast<const float4*>(bp + half * 4);
        float4 o;
        o.x = fmaxf(fmaf(acc[half * 4 + 0], di, fmaf(s4.x, d2, b4.x)), 0.f);
        o.y = fmaxf(fmaf(acc[half * 4 + 1], di, fmaf(s4.y, d2, b4.y)), 0.f);
        o.z = fmaxf(fmaf(acc[half * 4 + 2], di, fmaf(s4.z, d2, b4.z)), 0.f);
        o.w = fmaxf(fmaf(acc[half * 4 + 3], di, fmaf(s4.w, d2, b4.w)), 0.f);
        *reinterpret_cast<float4*>(outp + half * 4) = o;
    }
}

// ---------------------------------------------------------------------------
// 5) GEMM2: h2 = a1 @ W2 (fp32) ; h2h = fp16(h2 * dinv)
// ---------------------------------------------------------------------------
__global__ void k_gemm2(const float* __restrict__ W2, int n) {
    __shared__ float sW[D_HID * D_OUT];
    __shared__ float sx[8 * D_HID];
    int tid = threadIdx.x;
    for (int i = tid; i < D_HID * D_OUT; i += 256) sW[i] = W2[i];
    int node0 = blockIdx.x * 8;
    for (int i = tid; i < 8 * D_HID; i += 256) {
        int nn = node0 + i / D_HID;
        sx[i] = (nn < n) ? g_a1[nn * D_HID + (i % D_HID)] : 0.0f;
    }
    __syncthreads();
    int local = tid >> 5;
    int j     = tid & 31;
    int node  = node0 + local;
    if (node < n) {
        float acc = 0.0f;
        #pragma unroll
        for (int k = 0; k < D_HID; k++)
            acc = fmaf(sx[local * D_HID + k], sW[k * D_OUT + j], acc);
        g_h2 [node * D_OUT + j] = acc;
        g_h2h[node * D_OUT + j] = __float2half(acc * g_dinv[node]);
    }
}

// ---------------------------------------------------------------------------
// 6) gather layer 2: 8 threads/node, 4 cols each; fp16 output
// ---------------------------------------------------------------------------
__global__ void k_gather2(const float* __restrict__ b2, int n) {
    int lane = threadIdx.x & 31;
    int t    = lane & 7;
    int node = blockIdx.x * 32 + (threadIdx.x >> 3);
    if (node >= n) return;
    unsigned gmask = 0xFFu << (lane & 24);
    int beg = g_off[node];
    int end = beg + g_cnt[node];
    const uint2* rows = reinterpret_cast<const uint2*>(g_h2h);  // 8 uint2 / row
    float acc[4];
    #pragma unroll
    for (int k = 0; k < 4; k++) acc[k] = 0.0f;
    int nfull = (end - beg) & ~7;
    int i = beg;
    for (; i < beg + nfull; i += 8) {
        int e = g_csr[i + t];
        int ex[8];
        #pragma unroll
        for (int k = 0; k < 8; k++) ex[k] = __shfl_sync(gmask, e, k, 8);
        uint2 r[8];
        #pragma unroll
        for (int k = 0; k < 8; k++) r[k] = rows[ex[k] * 8 + t];
        #pragma unroll
        for (int k = 0; k < 8; k++) sum_row4(acc, r[k]);
    }
    if (i < end) {
        int e = (i + t < end) ? g_csr[i + t] : 0;
        int rem = end - i;
        #pragma unroll
        for (int k = 0; k < 8; k++) {
            if (k >= rem) break;
            int ex = __shfl_sync(gmask, e, k, 8);
            sum_row4(acc, rows[ex * 8 + t]);
        }
    }
    float di = g_dinv[node];
    float d2 = di * di;
    float4 s4 = *reinterpret_cast<const float4*>(g_h2 + node * D_OUT + t * 4);
    float4 b4 = *reinterpret_cast<const float4*>(b2 + t * 4);
    float o0 = fmaf(acc[0], di, fmaf(s4.x, d2, b4.x));
    float o1 = fmaf(acc[1], di, fmaf(s4.y, d2, b4.y));
    float o2 = fmaf(acc[2], di, fmaf(s4.z, d2, b4.z));
    float o3 = fmaf(acc[3], di, fmaf(s4.w, d2, b4.w));
    __half2 h0 = __floats2half2_rn(o0, o1);
    __half2 h1 = __floats2half2_rn(o2, o3);
    uint2 packed;
    packed.x = *reinterpret_cast<unsigned*>(&h0);
    packed.y = *reinterpret_cast<unsigned*>(&h1);
    reinterpret_cast<uint2*>(g_a2h)[node * 8 + t] = packed;
}

// ---------------------------------------------------------------------------
// 7) per-edge logits: one thread per edge, full fp16 rows, MLP=8
// ---------------------------------------------------------------------------
__global__ void k_logits(float* __restrict__ out, int E) {
    int e = blockIdx.x * blockDim.x + threadIdx.x;
    if (e >= E) return;
    int s = g_src[e];
    int d = g_dst[e];
    const uint4* rows = reinterpret_cast<const uint4*>(g_a2h);  // 4 uint4 / row
    uint4 rs[4], rd[4];
    #pragma unroll
    for (int k = 0; k < 4; k++) rs[k] = rows[s * 4 + k];
    #pragma unroll
    for (int k = 0; k < 4; k++) rd[k] = rows[d * 4 + k];
    float p = 0.0f;
    #pragma unroll
    for (int k = 0; k < 4; k++) {
        __half2* hs = reinterpret_cast<__half2*>(&rs[k]);
        __half2* hd = reinterpret_cast<__half2*>(&rd[k]);
        #pragma unroll
        for (int j = 0; j < 4; j++) {
            float2 fs = __half22float2(hs[j]);
            float2 fd = __half22float2(hd[j]);
            p = fmaf(fs.x, fd.x, p);
            p = fmaf(fs.y, fd.y, p);
        }
    }
    out[e] = p;
}

// ---------------------------------------------------------------------------
extern "C" void kernel_launch(void* const* d_in, const int* in_sizes, int n_in,
                              void* d_out, int out_size) {
    const float* x   = (const float*)d_in[0];
    const void*  ei  = d_in[1];
    const float* W1  = (const float*)d_in[2];
    const float* b1  = (const float*)d_in[3];
    const float* W2  = (const float*)d_in[4];
    const float* b2  = (const float*)d_in[5];
    float*       out = (float*)d_out;

    int N = in_sizes[0] / D_IN; if (N > N_NODES) N = N_NODES;
    int E = in_sizes[1] / 2;    if (E > MAX_E)   E = MAX_E;
    const int T = 256;

    k_init<<<(N + T - 1) / T, T>>>(ei, N);
    k_convert<<<(2 * E + T - 1) / T, T>>>(ei, E);
    k_scan<<<NLB, T>>>(N);

    int fb = (E + T - 1) / T;              // fill blocks
    int gb = (N + 3) / 4;                  // gemm1 blocks
    k_fill_gemm1<<<fb + gb, T>>>(E, x, W1, N, fb);

    k_gather1<<<(N + 31) / 32, T>>>(b1, N);
    k_gemm2<<<(N + 7) / 8, T>>>(W2, N);
    k_gather2<<<(N + 31) / 32, T>>>(b2, N);

    k_logits<<<(E + T - 1) / T, T>>>(out, E);
}

// round 13
// speedup vs baseline: 2.0881x; 2.0881x over previous
#include <cuda_runtime.h>
#include <cuda_fp16.h>

// GCN link predictor, CSR gather + prescaled fp16 rows + register-blocked GEMMs.
//   agg[d] = dinv[d] * sum( h[s]*dinv[s] )  (norm factorized)
//   h1 = x @ W1;  a1 = relu( dinv*sum(h1h[src]) + h1*dinv^2 + b1 )
//   h2 = a1 @ W2; a2h = fp16( dinv*sum(h2h[src]) + h2*dinv^2 + b2 )
//   logits[e] = dot(a2h[src], a2h[dst]) in fp32
//
// GEMMs: one thread per output column, W column in REGISTERS, x rows via
// broadcast LDS.128 -> 4 FMA per LDS (was 1 FMA per 2 LDS: the R10 bottleneck).
//
// NOTE: __device__ scratch arrays are ONLY referenced inside device code
// (host-side use of the symbol is UB and silently corrupts via ATS on GB300).

#define N_NODES 100000
#define MAX_E   1600000
#define D_IN    32
#define D_HID   64
#define D_OUT   32

#define LBCH    1024
#define NLB     ((N_NODES + LBCH - 1) / LBCH)

__device__ __align__(16) int    g_cnt [N_NODES];
__device__ __align__(16) int    g_off [N_NODES];
__device__ __align__(16) float  g_dinv[N_NODES];
__device__ __align__(16) float  g_h1  [N_NODES * D_HID];
__device__ __align__(16) __half g_h1h [N_NODES * D_HID];   // prescaled h1*dinv
__device__ __align__(16) float  g_a1  [N_NODES * D_HID];
__device__ __align__(16) float  g_h2  [N_NODES * D_OUT];
__device__ __align__(16) __half g_h2h [N_NODES * D_OUT];   // prescaled h2*dinv
__device__ __align__(16) __half g_a2h [N_NODES * D_OUT];
__device__ __align__(16) int    g_src [MAX_E];
__device__ __align__(16) int    g_dst [MAX_E];
__device__ __align__(16) int    g_pos [MAX_E];
__device__ __align__(16) int    g_csr [MAX_E];             // src index only
__device__ unsigned long long   g_lb  [NLB];
__device__ unsigned int         g_ticket;
__device__ int                  g_is64;

// ---------------------------------------------------------------------------
// 0) init
// ---------------------------------------------------------------------------
__global__ void k_init(const void* __restrict__ ei, int n) {
    int i = blockIdx.x * blockDim.x + threadIdx.x;
    if (i < n) g_cnt[i] = 0;
    if (i < NLB) g_lb[i] = 0ull;
    if (i == 0) {
        g_ticket = 0u;
        const long long* p = (const long long*)ei;
        int is64 = 1;
        #pragma unroll
        for (int k = 0; k < 8; k++) {
            long long v = p[k];
            if (v < 0 || v >= N_NODES) is64 = 0;
        }
        g_is64 = is64;
    }
}

// ---------------------------------------------------------------------------
// 1) convert + degree histogram
// ---------------------------------------------------------------------------
__global__ void k_convert(const void* __restrict__ ei, int E) {
    int i = blockIdx.x * blockDim.x + threadIdx.x;
    if (i >= 2 * E) return;
    int v;
    if (g_is64) v = (int)((const long long*)ei)[i];
    else        v = ((const int*)ei)[i];
    v = min(max(v, 0), N_NODES - 1);
    if (i < E) {
        g_src[i] = v;
    } else {
        int e = i - E;
        g_dst[e] = v;
        g_pos[e] = atomicAdd(&g_cnt[v], 1);
    }
}

// ---------------------------------------------------------------------------
// 2) decoupled-lookback exclusive scan (+ fused dinv)
// ---------------------------------------------------------------------------
__global__ void k_scan(int n) {
    __shared__ int sh[256];
    __shared__ int s_bid;
    __shared__ int s_excl;
    int t = threadIdx.x;
    if (t == 0) s_bid = (int)atomicAdd(&g_ticket, 1u);
    __syncthreads();
    int bid  = s_bid;
    int base = bid * LBCH + t * 4;

    int4 c4 = make_int4(0, 0, 0, 0);
    if (base + 3 < n) {
        c4 = *reinterpret_cast<const int4*>(g_cnt + base);
    } else {
        int* cp = (int*)&c4;
        #pragma unroll
        for (int k = 0; k < 4; k++) cp[k] = (base + k < n) ? g_cnt[base + k] : 0;
    }
    int lsum = c4.x + c4.y + c4.z + c4.w;
    sh[t] = lsum;
    __syncthreads();
    #pragma unroll
    for (int d = 1; d < 256; d <<= 1) {
        int v = (t >= d) ? sh[t - d] : 0;
        __syncthreads();
        sh[t] += v;
        __syncthreads();
    }
    int total = sh[255];
    int texcl = sh[t] - lsum;

    if (t == 0) {
        atomicExch(&g_lb[bid], ((unsigned long long)total << 2) | 1ull);
        long long excl = 0;
        int j = bid - 1;
        while (j >= 0) {
            unsigned long long v;
            do { v = atomicAdd(&g_lb[j], 0ull); } while ((v & 3ull) == 0ull);
            excl += (long long)(v >> 2);
            if ((v & 3ull) == 2ull) break;
            j--;
        }
        atomicExch(&g_lb[bid], ((unsigned long long)(excl + total) << 2) | 2ull);
        s_excl = (int)excl;
    }
    __syncthreads();
    int run = s_excl + texcl;

    int off[4];
    off[0] = run;
    off[1] = off[0] + c4.x;
    off[2] = off[1] + c4.y;
    off[3] = off[2] + c4.z;
    if (base + 3 < n) {
        *reinterpret_cast<int4*>(g_off + base) = *reinterpret_cast<int4*>(off);
        float4 dv = make_float4(rsqrtf((float)(c4.x + 1)), rsqrtf((float)(c4.y + 1)),
                                rsqrtf((float)(c4.z + 1)), rsqrtf((float)(c4.w + 1)));
        *reinterpret_cast<float4*>(g_dinv + base) = dv;
    } else {
        int* cp = (int*)&c4;
        #pragma unroll
        for (int k = 0; k < 4; k++) if (base + k < n) {
            g_off[base + k]  = off[k];
            g_dinv[base + k] = rsqrtf((float)(cp[k] + 1));
        }
    }
}

// ---------------------------------------------------------------------------
// 3) FUSED: CSR fill (blocks [0,fb)) || register-blocked GEMM1 (rest)
//    GEMM1: 64 nodes/block; thread owns col j=tid&63, node-lane tid>>6;
//    W1 column in 32 regs, x rows via broadcast LDS.128.
// ---------------------------------------------------------------------------
__global__ void __launch_bounds__(256) k_fill_gemm1(
        int E, const float* __restrict__ x, const float* __restrict__ W1,
        int n, int fb) {
    __shared__ float sx[64 * D_IN];      // 8 KB
    __shared__ float sW[D_IN * D_HID];   // 8 KB

    int tid = threadIdx.x;
    if ((int)blockIdx.x < fb) {
        int e = blockIdx.x * blockDim.x + tid;
        if (e >= E) return;
        g_csr[g_off[g_dst[e]] + g_pos[e]] = g_src[e];
        return;
    }

    int bid   = blockIdx.x - fb;
    int node0 = bid * 64;

    // load x tile (64 nodes x 32) + W1, both contiguous, float4 coalesced
    if (node0 + 64 <= n) {
        const float4* xg = reinterpret_cast<const float4*>(x + node0 * D_IN);
        #pragma unroll
        for (int i = 0; i < 2; i++)
            reinterpret_cast<float4*>(sx)[tid + i * 256] = xg[tid + i * 256];
    } else {
        for (int i = tid; i < 64 * D_IN; i += 256) {
            int nn = node0 + i / D_IN;
            sx[i] = (nn < n) ? x[nn * D_IN + (i % D_IN)] : 0.0f;
        }
    }
    {
        const float4* wg = reinterpret_cast<const float4*>(W1);
        #pragma unroll
        for (int i = 0; i < 2; i++)
            reinterpret_cast<float4*>(sW)[tid + i * 256] = wg[tid + i * 256];
    }
    __syncthreads();

    int j  = tid & 63;
    int nl = tid >> 6;          // 0..3
    float w[D_IN];
    #pragma unroll
    for (int k = 0; k < D_IN; k++) w[k] = sW[k * D_HID + j];

    #pragma unroll 4
    for (int m = nl; m < 64; m += 4) {
        int node = node0 + m;
        if (node >= n) break;
        float acc = 0.0f;
        #pragma unroll
        for (int kk = 0; kk < D_IN / 4; kk++) {
            float4 xv = *reinterpret_cast<const float4*>(sx + m * D_IN + kk * 4);
            acc = fmaf(xv.x, w[4 * kk + 0], acc);
            acc = fmaf(xv.y, w[4 * kk + 1], acc);
            acc = fmaf(xv.z, w[4 * kk + 2], acc);
            acc = fmaf(xv.w, w[4 * kk + 3], acc);
        }
        float di = g_dinv[node];
        g_h1 [node * D_HID + j] = acc;
        g_h1h[node * D_HID + j] = __float2half(acc * di);
    }
}

// ---------------------------------------------------------------------------
// fp16 sum helpers (rows are prescaled — pure summation)
// ---------------------------------------------------------------------------
__device__ __forceinline__ void sum_row8(float* acc, uint4 r) {
    __half2* h = reinterpret_cast<__half2*>(&r);
    #pragma unroll
    for (int k = 0; k < 4; k++) {
        float2 f = __half22float2(h[k]);
        acc[2 * k + 0] += f.x;
        acc[2 * k + 1] += f.y;
    }
}

__device__ __forceinline__ void sum_row4(float* acc, uint2 r) {
    __half2* h = reinterpret_cast<__half2*>(&r);
    #pragma unroll
    for (int k = 0; k < 2; k++) {
        float2 f = __half22float2(h[k]);
        acc[2 * k + 0] += f.x;
        acc[2 * k + 1] += f.y;
    }
}

// ---------------------------------------------------------------------------
// 4) gather layer 1: 8 threads/node, 8 cols each; 8-edge two-phase batches
// ---------------------------------------------------------------------------
__global__ void k_gather1(const float* __restrict__ b1, int n) {
    int lane = threadIdx.x & 31;
    int t    = lane & 7;
    int node = blockIdx.x * 32 + (threadIdx.x >> 3);
    if (node >= n) return;
    unsigned gmask = 0xFFu << (lane & 24);
    int beg = g_off[node];
    int end = beg + g_cnt[node];
    const uint4* rows = reinterpret_cast<const uint4*>(g_h1h);
    float acc[8];
    #pragma unroll
    for (int k = 0; k < 8; k++) acc[k] = 0.0f;
    int nfull = (end - beg) & ~7;
    int i = beg;
    for (; i < beg + nfull; i += 8) {
        int e = g_csr[i + t];
        int ex[8];
        #pragma unroll
        for (int k = 0; k < 8; k++) ex[k] = __shfl_sync(gmask, e, k, 8);
        uint4 r[8];
        #pragma unroll
        for (int k = 0; k < 8; k++) r[k] = rows[ex[k] * 8 + t];
        #pragma unroll
        for (int k = 0; k < 8; k++) sum_row8(acc, r[k]);
    }
    if (i < end) {
        int e = (i + t < end) ? g_csr[i + t] : 0;
        int rem = end - i;
        #pragma unroll
        for (int k = 0; k < 8; k++) {
            if (k >= rem) break;
            int ex = __shfl_sync(gmask, e, k, 8);
            sum_row8(acc, rows[ex * 8 + t]);
        }
    }
    float di = g_dinv[node];
    float d2 = di * di;
    const float* selfp = g_h1 + node * D_HID + t * 8;
    const float* bp    = b1 + t * 8;
    float* outp        = g_a1 + node * D_HID + t * 8;
    #pragma unroll
    for (int half = 0; half < 2; half++) {
        float4 s4 = *reinterpret_cast<const float4*>(selfp + half * 4);
        float4 b4 = *reinterpret_cast<const float4*>(bp + half * 4);
        float4 o;
        o.x = fmaxf(fmaf(acc[half * 4 + 0], di, fmaf(s4.x, d2, b4.x)), 0.f);
        o.y = fmaxf(fmaf(acc[half * 4 + 1], di, fmaf(s4.y, d2, b4.y)), 0.f);
        o.z = fmaxf(fmaf(acc[half * 4 + 2], di, fmaf(s4.z, d2, b4.z)), 0.f);
        o.w = fmaxf(fmaf(acc[half * 4 + 3], di, fmaf(s4.w, d2, b4.w)), 0.f);
        *reinterpret_cast<float4*>(outp + half * 4) = o;
    }
}

// ---------------------------------------------------------------------------
// 5) register-blocked GEMM2: 64 nodes/block; warp = 32 cols of one node;
//    W2 column in 64 regs, a1 rows via broadcast LDS.128.
// ---------------------------------------------------------------------------
__global__ void __launch_bounds__(256) k_gemm2(const float* __restrict__ W2, int n) {
    __shared__ float sa[64 * D_HID];     // 16 KB
    __shared__ float sW[D_HID * D_OUT];  // 8 KB
    int tid   = threadIdx.x;
    int node0 = blockIdx.x * 64;

    // a1 tile: 64 nodes x 64 floats = 4096 floats, contiguous
    {
        const float4* ag = reinterpret_cast<const float4*>(g_a1 + node0 * D_HID);
        int limit = min(64, n - node0) * (D_HID / 4);
        #pragma unroll
        for (int i = 0; i < 4; i++) {
            int idx = tid + i * 256;
            if (idx < limit) reinterpret_cast<float4*>(sa)[idx] = ag[idx];
        }
    }
    {
        const float4* wg = reinterpret_cast<const float4*>(W2);
        #pragma unroll
        for (int i = 0; i < 2; i++)
            reinterpret_cast<float4*>(sW)[tid + i * 256] = wg[tid + i * 256];
    }
    __syncthreads();

    int j  = tid & 31;
    int nl = tid >> 5;          // 0..7
    float w[D_HID];
    #pragma unroll
    for (int k = 0; k < D_HID; k++) w[k] = sW[k * D_OUT + j];

    #pragma unroll 2
    for (int m = nl; m < 64; m += 8) {
        int node = node0 + m;
        if (node >= n) break;
        float acc = 0.0f;
        #pragma unroll
        for (int kk = 0; kk < D_HID / 4; kk++) {
            float4 xv = *reinterpret_cast<const float4*>(sa + m * D_HID + kk * 4);
            acc = fmaf(xv.x, w[4 * kk + 0], acc);
            acc = fmaf(xv.y, w[4 * kk + 1], acc);
            acc = fmaf(xv.z, w[4 * kk + 2], acc);
            acc = fmaf(xv.w, w[4 * kk + 3], acc);
        }
        float di = g_dinv[node];
        g_h2 [node * D_OUT + j] = acc;
        g_h2h[node * D_OUT + j] = __float2half(acc * di);
    }
}

// ---------------------------------------------------------------------------
// 6) gather layer 2: 8 threads/node, 4 cols each; fp16 output
// ---------------------------------------------------------------------------
__global__ void k_gather2(const float* __restrict__ b2, int n) {
    int lane = threadIdx.x & 31;
    int t    = lane & 7;
    int node = blockIdx.x * 32 + (threadIdx.x >> 3);
    if (node >= n) return;
    unsigned gmask = 0xFFu << (lane & 24);
    int beg = g_off[node];
    int end = beg + g_cnt[node];
    const uint2* rows = reinterpret_cast<const uint2*>(g_h2h);
    float acc[4];
    #pragma unroll
    for (int k = 0; k < 4; k++) acc[k] = 0.0f;
    int nfull = (end - beg) & ~7;
    int i = beg;
    for (; i < beg + nfull; i += 8) {
        int e = g_csr[i + t];
        int ex[8];
        #pragma unroll
        for (int k = 0; k < 8; k++) ex[k] = __shfl_sync(gmask, e, k, 8);
        uint2 r[8];
        #pragma unroll
        for (int k = 0; k < 8; k++) r[k] = rows[ex[k] * 8 + t];
        #pragma unroll
        for (int k = 0; k < 8; k++) sum_row4(acc, r[k]);
    }
    if (i < end) {
        int e = (i + t < end) ? g_csr[i + t] : 0;
        int rem = end - i;
        #pragma unroll
        for (int k = 0; k < 8; k++) {
            if (k >= rem) break;
            int ex = __shfl_sync(gmask, e, k, 8);
            sum_row4(acc, rows[ex * 8 + t]);
        }
    }
    float di = g_dinv[node];
    float d2 = di * di;
    float4 s4 = *reinterpret_cast<const float4*>(g_h2 + node * D_OUT + t * 4);
    float4 b4 = *reinterpret_cast<const float4*>(b2 + t * 4);
    float o0 = fmaf(acc[0], di, fmaf(s4.x, d2, b4.x));
    float o1 = fmaf(acc[1], di, fmaf(s4.y, d2, b4.y));
    float o2 = fmaf(acc[2], di, fmaf(s4.z, d2, b4.z));
    float o3 = fmaf(acc[3], di, fmaf(s4.w, d2, b4.w));
    __half2 h0 = __floats2half2_rn(o0, o1);
    __half2 h1 = __floats2half2_rn(o2, o3);
    uint2 packed;
    packed.x = *reinterpret_cast<unsigned*>(&h0);
    packed.y = *reinterpret_cast<unsigned*>(&h1);
    reinterpret_cast<uint2*>(g_a2h)[node * 8 + t] = packed;
}

// ---------------------------------------------------------------------------
// 7) per-edge logits: one thread per edge, full fp16 rows, MLP=8
// ---------------------------------------------------------------------------
__global__ void k_logits(float* __restrict__ out, int E) {
    int e = blockIdx.x * blockDim.x + threadIdx.x;
    if (e >= E) return;
    int s = g_src[e];
    int d = g_dst[e];
    const uint4* rows = reinterpret_cast<const uint4*>(g_a2h);
    uint4 rs[4], rd[4];
    #pragma unroll
    for (int k = 0; k < 4; k++) rs[k] = rows[s * 4 + k];
    #pragma unroll
    for (int k = 0; k < 4; k++) rd[k] = rows[d * 4 + k];
    float p = 0.0f;
    #pragma unroll
    for (int k = 0; k < 4; k++) {
        __half2* hs = reinterpret_cast<__half2*>(&rs[k]);
        __half2* hd = reinterpret_cast<__half2*>(&rd[k]);
        #pragma unroll
        for (int j = 0; j < 4; j++) {
            float2 fs = __half22float2(hs[j]);
            float2 fd = __half22float2(hd[j]);
            p = fmaf(fs.x, fd.x, p);
            p = fmaf(fs.y, fd.y, p);
        }
    }
    out[e] = p;
}

// ---------------------------------------------------------------------------
extern "C" void kernel_launch(void* const* d_in, const int* in_sizes, int n_in,
                              void* d_out, int out_size) {
    const float* x   = (const float*)d_in[0];
    const void*  ei  = d_in[1];
    const float* W1  = (const float*)d_in[2];
    const float* b1  = (const float*)d_in[3];
    const float* W2  = (const float*)d_in[4];
    const float* b2  = (const float*)d_in[5];
    float*       out = (float*)d_out;

    int N = in_sizes[0] / D_IN; if (N > N_NODES) N = N_NODES;
    int E = in_sizes[1] / 2;    if (E > MAX_E)   E = MAX_E;
    const int T = 256;

    k_init<<<(N + T - 1) / T, T>>>(ei, N);
    k_convert<<<(2 * E + T - 1) / T, T>>>(ei, E);
    k_scan<<<NLB, T>>>(N);

    int fb = (E + T - 1) / T;              // fill blocks
    int gb = (N + 63) / 64;                // gemm1 blocks
    k_fill_gemm1<<<fb + gb, T>>>(E, x, W1, N, fb);

    k_gather1<<<(N + 31) / 32, T>>>(b1, N);
    k_gemm2<<<(N + 63) / 64, T>>>(W2, N);
    k_gather2<<<(N + 31) / 32, T>>>(b2, N);

    k_logits<<<(E + T - 1) / T, T>>>(out, E);
}

// round 14
// speedup vs baseline: 2.1705x; 1.0395x over previous
#include <cuda_runtime.h>
#include <cuda_fp16.h>

// GCN link predictor, CSR gather + prescaled fp16 everywhere + reg-blocked GEMMs.
//   agg[d] = dinv[d] * ( sum_{s in N(d)} h[s]*dinv[s] + h[d]*dinv[d] )
//   -> self term is just the node's OWN prescaled row added into the sum.
//   h1h = fp16((x@W1)*dinv); a1h = fp16(relu(dinv*sum(h1h rows) + b1))
//   h2h = fp16((a1@W2)*dinv); a2h = fp16(dinv*sum(h2h rows) + b2)
//   logits[e] = dot(a2h[src], a2h[dst]) in fp32
//
// NOTE: __device__ scratch arrays are ONLY referenced inside device code
// (host-side use of the symbol is UB and silently corrupts via ATS on GB300).

#define N_NODES 100000
#define MAX_E   1600000
#define D_IN    32
#define D_HID   64
#define D_OUT   32

#define LBCH    1024
#define NLB     ((N_NODES + LBCH - 1) / LBCH)

__device__ __align__(16) int    g_cnt [N_NODES];
__device__ __align__(16) int    g_off [N_NODES];
__device__ __align__(16) float  g_dinv[N_NODES];
__device__ __align__(16) __half g_h1h [N_NODES * D_HID];   // fp16(h1*dinv)
__device__ __align__(16) __half g_a1h [N_NODES * D_HID];   // fp16 a1
__device__ __align__(16) __half g_h2h [N_NODES * D_OUT];   // fp16(h2*dinv)
__device__ __align__(16) __half g_a2h [N_NODES * D_OUT];   // fp16 a2
__device__ __align__(16) int    g_src [MAX_E];
__device__ __align__(16) int    g_dst [MAX_E];
__device__ __align__(16) int    g_pos [MAX_E];
__device__ __align__(16) int    g_csr [MAX_E];             // src index only
__device__ unsigned long long   g_lb  [NLB];
__device__ unsigned int         g_ticket;
__device__ int                  g_is64;

// ---------------------------------------------------------------------------
// 0) init
// ---------------------------------------------------------------------------
__global__ void k_init(const void* __restrict__ ei, int n) {
    int i = blockIdx.x * blockDim.x + threadIdx.x;
    if (i < n) g_cnt[i] = 0;
    if (i < NLB) g_lb[i] = 0ull;
    if (i == 0) {
        g_ticket = 0u;
        const long long* p = (const long long*)ei;
        int is64 = 1;
        #pragma unroll
        for (int k = 0; k < 8; k++) {
            long long v = p[k];
            if (v < 0 || v >= N_NODES) is64 = 0;
        }
        g_is64 = is64;
    }
}

// ---------------------------------------------------------------------------
// 1) convert (2 elements/thread, vector loads) + degree histogram
// ---------------------------------------------------------------------------
__global__ void k_convert(const void* __restrict__ ei, int E) {
    int i = blockIdx.x * blockDim.x + threadIdx.x;   // pair index
    int base = i * 2;
    if (base >= 2 * E) return;
    int v0, v1;
    if (g_is64) {
        longlong2 p = ((const longlong2*)ei)[i];
        v0 = (int)p.x; v1 = (int)p.y;
    } else {
        int2 p = ((const int2*)ei)[i];
        v0 = p.x; v1 = p.y;
    }
    v0 = min(max(v0, 0), N_NODES - 1);
    v1 = min(max(v1, 0), N_NODES - 1);
    if (base < E) {                       // E is even: pair never straddles
        *reinterpret_cast<int2*>(g_src + base) = make_int2(v0, v1);
    } else {
        int e = base - E;
        *reinterpret_cast<int2*>(g_dst + e) = make_int2(v0, v1);
        int p0 = atomicAdd(&g_cnt[v0], 1);
        int p1 = atomicAdd(&g_cnt[v1], 1);
        *reinterpret_cast<int2*>(g_pos + e) = make_int2(p0, p1);
    }
}

// ---------------------------------------------------------------------------
// 2) decoupled-lookback exclusive scan (+ fused dinv)
// ---------------------------------------------------------------------------
__global__ void k_scan(int n) {
    __shared__ int sh[256];
    __shared__ int s_bid;
    __shared__ int s_excl;
    int t = threadIdx.x;
    if (t == 0) s_bid = (int)atomicAdd(&g_ticket, 1u);
    __syncthreads();
    int bid  = s_bid;
    int base = bid * LBCH + t * 4;

    int4 c4 = make_int4(0, 0, 0, 0);
    if (base + 3 < n) {
        c4 = *reinterpret_cast<const int4*>(g_cnt + base);
    } else {
        int* cp = (int*)&c4;
        #pragma unroll
        for (int k = 0; k < 4; k++) cp[k] = (base + k < n) ? g_cnt[base + k] : 0;
    }
    int lsum = c4.x + c4.y + c4.z + c4.w;
    sh[t] = lsum;
    __syncthreads();
    #pragma unroll
    for (int d = 1; d < 256; d <<= 1) {
        int v = (t >= d) ? sh[t - d] : 0;
        __syncthreads();
        sh[t] += v;
        __syncthreads();
    }
    int total = sh[255];
    int texcl = sh[t] - lsum;

    if (t == 0) {
        atomicExch(&g_lb[bid], ((unsigned long long)total << 2) | 1ull);
        long long excl = 0;
        int j = bid - 1;
        while (j >= 0) {
            unsigned long long v;
            do { v = atomicAdd(&g_lb[j], 0ull); } while ((v & 3ull) == 0ull);
            excl += (long long)(v >> 2);
            if ((v & 3ull) == 2ull) break;
            j--;
        }
        atomicExch(&g_lb[bid], ((unsigned long long)(excl + total) << 2) | 2ull);
        s_excl = (int)excl;
    }
    __syncthreads();
    int run = s_excl + texcl;

    int off[4];
    off[0] = run;
    off[1] = off[0] + c4.x;
    off[2] = off[1] + c4.y;
    off[3] = off[2] + c4.z;
    if (base + 3 < n) {
        *reinterpret_cast<int4*>(g_off + base) = *reinterpret_cast<int4*>(off);
        float4 dv = make_float4(rsqrtf((float)(c4.x + 1)), rsqrtf((float)(c4.y + 1)),
                                rsqrtf((float)(c4.z + 1)), rsqrtf((float)(c4.w + 1)));
        *reinterpret_cast<float4*>(g_dinv + base) = dv;
    } else {
        int* cp = (int*)&c4;
        #pragma unroll
        for (int k = 0; k < 4; k++) if (base + k < n) {
            g_off[base + k]  = off[k];
            g_dinv[base + k] = rsqrtf((float)(cp[k] + 1));
        }
    }
}

// ---------------------------------------------------------------------------
// 3) FUSED: CSR fill (blocks [0,fb)) || register-blocked GEMM1 (rest)
//    GEMM1 writes ONLY prescaled fp16 rows.
// ---------------------------------------------------------------------------
__global__ void __launch_bounds__(256) k_fill_gemm1(
        int E, const float* __restrict__ x, const float* __restrict__ W1,
        int n, int fb) {
    __shared__ float sx[64 * D_IN];      // 8 KB
    __shared__ float sW[D_IN * D_HID];   // 8 KB

    int tid = threadIdx.x;
    if ((int)blockIdx.x < fb) {
        int e = blockIdx.x * blockDim.x + tid;
        if (e >= E) return;
        g_csr[g_off[g_dst[e]] + g_pos[e]] = g_src[e];
        return;
    }

    int bid   = blockIdx.x - fb;
    int node0 = bid * 64;

    if (node0 + 64 <= n) {
        const float4* xg = reinterpret_cast<const float4*>(x + node0 * D_IN);
        #pragma unroll
        for (int i = 0; i < 2; i++)
            reinterpret_cast<float4*>(sx)[tid + i * 256] = xg[tid + i * 256];
    } else {
        for (int i = tid; i < 64 * D_IN; i += 256) {
            int nn = node0 + i / D_IN;
            sx[i] = (nn < n) ? x[nn * D_IN + (i % D_IN)] : 0.0f;
        }
    }
    {
        const float4* wg = reinterpret_cast<const float4*>(W1);
        #pragma unroll
        for (int i = 0; i < 2; i++)
            reinterpret_cast<float4*>(sW)[tid + i * 256] = wg[tid + i * 256];
    }
    __syncthreads();

    int j  = tid & 63;
    int nl = tid >> 6;          // 0..3
    float w[D_IN];
    #pragma unroll
    for (int k = 0; k < D_IN; k++) w[k] = sW[k * D_HID + j];

    #pragma unroll 4
    for (int m = nl; m < 64; m += 4) {
        int node = node0 + m;
        if (node >= n) break;
        float acc = 0.0f;
        #pragma unroll
        for (int kk = 0; kk < D_IN / 4; kk++) {
            float4 xv = *reinterpret_cast<const float4*>(sx + m * D_IN + kk * 4);
            acc = fmaf(xv.x, w[4 * kk + 0], acc);
            acc = fmaf(xv.y, w[4 * kk + 1], acc);
            acc = fmaf(xv.z, w[4 * kk + 2], acc);
            acc = fmaf(xv.w, w[4 * kk + 3], acc);
        }
        g_h1h[node * D_HID + j] = __float2half(acc * g_dinv[node]);
    }
}

// ---------------------------------------------------------------------------
// fp16 sum helpers (rows are prescaled — pure summation)
// ---------------------------------------------------------------------------
__device__ __forceinline__ void sum_row8(float* acc, uint4 r) {
    __half2* h = reinterpret_cast<__half2*>(&r);
    #pragma unroll
    for (int k = 0; k < 4; k++) {
        float2 f = __half22float2(h[k]);
        acc[2 * k + 0] += f.x;
        acc[2 * k + 1] += f.y;
    }
}

__device__ __forceinline__ void sum_row4(float* acc, uint2 r) {
    __half2* h = reinterpret_cast<__half2*>(&r);
    #pragma unroll
    for (int k = 0; k < 2; k++) {
        float2 f = __half22float2(h[k]);
        acc[2 * k + 0] += f.x;
        acc[2 * k + 1] += f.y;
    }
}

// ---------------------------------------------------------------------------
// 4) gather layer 1: 8 threads/node, 8 cols each; self row folded into sum;
//    fp16 a1 output
// ---------------------------------------------------------------------------
__global__ void k_gather1(const float* __restrict__ b1, int n) {
    int lane = threadIdx.x & 31;
    int t    = lane & 7;
    int node = blockIdx.x * 32 + (threadIdx.x >> 3);
    if (node >= n) return;
    unsigned gmask = 0xFFu << (lane & 24);
    int beg = g_off[node];
    int end = beg + g_cnt[node];
    const uint4* rows = reinterpret_cast<const uint4*>(g_h1h);  // 8 uint4 / row
    float acc[8];
    #pragma unroll
    for (int k = 0; k < 8; k++) acc[k] = 0.0f;
    int nfull = (end - beg) & ~7;
    int i = beg;
    for (; i < beg + nfull; i += 8) {
        int e = g_csr[i + t];
        int ex[8];
        #pragma unroll
        for (int k = 0; k < 8; k++) ex[k] = __shfl_sync(gmask, e, k, 8);
        uint4 r[8];
        #pragma unroll
        for (int k = 0; k < 8; k++) r[k] = rows[ex[k] * 8 + t];
        #pragma unroll
        for (int k = 0; k < 8; k++) sum_row8(acc, r[k]);
    }
    if (i < end) {
        int e = (i + t < end) ? g_csr[i + t] : 0;
        int rem = end - i;
        #pragma unroll
        for (int k = 0; k < 8; k++) {
            if (k >= rem) break;
            int ex = __shfl_sync(gmask, e, k, 8);
            sum_row8(acc, rows[ex * 8 + t]);
        }
    }
    sum_row8(acc, rows[node * 8 + t]);      // self-loop term (own prescaled row)
    float di = g_dinv[node];
    const float* bp = b1 + t * 8;
    float o[8];
    #pragma unroll
    for (int half = 0; half < 2; half++) {
        float4 b4 = *reinterpret_cast<const float4*>(bp + half * 4);
        o[half * 4 + 0] = fmaxf(fmaf(acc[half * 4 + 0], di, b4.x), 0.f);
        o[half * 4 + 1] = fmaxf(fmaf(acc[half * 4 + 1], di, b4.y), 0.f);
        o[half * 4 + 2] = fmaxf(fmaf(acc[half * 4 + 2], di, b4.z), 0.f);
        o[half * 4 + 3] = fmaxf(fmaf(acc[half * 4 + 3], di, b4.w), 0.f);
    }
    uint4 packed;
    unsigned* pp = reinterpret_cast<unsigned*>(&packed);
    #pragma unroll
    for (int k = 0; k < 4; k++) {
        __half2 h = __floats2half2_rn(o[2 * k], o[2 * k + 1]);
        pp[k] = *reinterpret_cast<unsigned*>(&h);
    }
    reinterpret_cast<uint4*>(g_a1h)[node * 8 + t] = packed;
}

// ---------------------------------------------------------------------------
// 5) register-blocked GEMM2: fp16 a1 in, fp16 prescaled h2 out
// ---------------------------------------------------------------------------
__global__ void __launch_bounds__(256) k_gemm2(const float* __restrict__ W2, int n) {
    __shared__ float sa[64 * D_HID];     // 16 KB (fp32 converted)
    __shared__ float sW[D_HID * D_OUT];  // 8 KB
    int tid   = threadIdx.x;
    int node0 = blockIdx.x * 64;

    // a1h tile: 64 nodes x 64 halves = 512 uint4; convert to fp32 in smem
    {
        const uint4* ag = reinterpret_cast<const uint4*>(g_a1h) + node0 * 8;
        int limit = min(64, n - node0) * 8;
        #pragma unroll
        for (int i = 0; i < 2; i++) {
            int idx = tid + i * 256;
            if (idx < limit) {
                uint4 r = ag[idx];
                __half2* h = reinterpret_cast<__half2*>(&r);
                float* dst = sa + idx * 8;
                #pragma unroll
                for (int k = 0; k < 4; k++) {
                    float2 f = __half22float2(h[k]);
                    dst[2 * k + 0] = f.x;
                    dst[2 * k + 1] = f.y;
                }
            }
        }
    }
    {
        const float4* wg = reinterpret_cast<const float4*>(W2);
        #pragma unroll
        for (int i = 0; i < 2; i++)
            reinterpret_cast<float4*>(sW)[tid + i * 256] = wg[tid + i * 256];
    }
    __syncthreads();

    int j  = tid & 31;
    int nl = tid >> 5;          // 0..7
    float w[D_HID];
    #pragma unroll
    for (int k = 0; k < D_HID; k++) w[k] = sW[k * D_OUT + j];

    #pragma unroll 2
    for (int m = nl; m < 64; m += 8) {
        int node = node0 + m;
        if (node >= n) break;
        float acc = 0.0f;
        #pragma unroll
        for (int kk = 0; kk < D_HID / 4; kk++) {
            float4 xv = *reinterpret_cast<const float4*>(sa + m * D_HID + kk * 4);
            acc = fmaf(xv.x, w[4 * kk + 0], acc);
            acc = fmaf(xv.y, w[4 * kk + 1], acc);
            acc = fmaf(xv.z, w[4 * kk + 2], acc);
            acc = fmaf(xv.w, w[4 * kk + 3], acc);
        }
        g_h2h[node * D_OUT + j] = __float2half(acc * g_dinv[node]);
    }
}

// ---------------------------------------------------------------------------
// 6) gather layer 2: 8 threads/node, 4 cols each; self row folded; fp16 a2
// ---------------------------------------------------------------------------
__global__ void k_gather2(const float* __restrict__ b2, int n) {
    int lane = threadIdx.x & 31;
    int t    = lane & 7;
    int node = blockIdx.x * 32 + (threadIdx.x >> 3);
    if (node >= n) return;
    unsigned gmask = 0xFFu << (lane & 24);
    int beg = g_off[node];
    int end = beg + g_cnt[node];
    const uint2* rows = reinterpret_cast<const uint2*>(g_h2h);  // 8 uint2 / row
    float acc[4];
    #pragma unroll
    for (int k = 0; k < 4; k++) acc[k] = 0.0f;
    int nfull = (end - beg) & ~7;
    int i = beg;
    for (; i < beg + nfull; i += 8) {
        int e = g_csr[i + t];
        int ex[8];
        #pragma unroll
        for (int k = 0; k < 8; k++) ex[k] = __shfl_sync(gmask, e, k, 8);
        uint2 r[8];
        #pragma unroll
        for (int k = 0; k < 8; k++) r[k] = rows[ex[k] * 8 + t];
        #pragma unroll
        for (int k = 0; k < 8; k++) sum_row4(acc, r[k]);
    }
    if (i < end) {
        int e = (i + t < end) ? g_csr[i + t] : 0;
        int rem = end - i;
        #pragma unroll
        for (int k = 0; k < 8; k++) {
            if (k >= rem) break;
            int ex = __shfl_sync(gmask, e, k, 8);
            sum_row4(acc, rows[ex * 8 + t]);
        }
    }
    sum_row4(acc, rows[node * 8 + t]);      // self-loop term
    float di = g_dinv[node];
    float4 b4 = *reinterpret_cast<const float4*>(b2 + t * 4);
    float o0 = fmaf(acc[0], di, b4.x);
    float o1 = fmaf(acc[1], di, b4.y);
    float o2 = fmaf(acc[2], di, b4.z);
    float o3 = fmaf(acc[3], di, b4.w);
    __half2 h0 = __floats2half2_rn(o0, o1);
    __half2 h1 = __floats2half2_rn(o2, o3);
    uint2 packed;
    packed.x = *reinterpret_cast<unsigned*>(&h0);
    packed.y = *reinterpret_cast<unsigned*>(&h1);
    reinterpret_cast<uint2*>(g_a2h)[node * 8 + t] = packed;
}

// ---------------------------------------------------------------------------
// 7) per-edge logits: one thread per edge, full fp16 rows, MLP=8
// ---------------------------------------------------------------------------
__global__ void k_logits(float* __restrict__ out, int E) {
    int e = blockIdx.x * blockDim.x + threadIdx.x;
    if (e >= E) return;
    int s = g_src[e];
    int d = g_dst[e];
    const uint4* rows = reinterpret_cast<const uint4*>(g_a2h);
    uint4 rs[4], rd[4];
    #pragma unroll
    for (int k = 0; k < 4; k++) rs[k] = rows[s * 4 + k];
    #pragma unroll
    for (int k = 0; k < 4; k++) rd[k] = rows[d * 4 + k];
    float p = 0.0f;
    #pragma unroll
    for (int k = 0; k < 4; k++) {
        __half2* hs = reinterpret_cast<__half2*>(&rs[k]);
        __half2* hd = reinterpret_cast<__half2*>(&rd[k]);
        #pragma unroll
        for (int j = 0; j < 4; j++) {
            float2 fs = __half22float2(hs[j]);
            float2 fd = __half22float2(hd[j]);
            p = fmaf(fs.x, fd.x, p);
            p = fmaf(fs.y, fd.y, p);
        }
    }
    out[e] = p;
}

// ---------------------------------------------------------------------------
extern "C" void kernel_launch(void* const* d_in, const int* in_sizes, int n_in,
                              void* d_out, int out_size) {
    const float* x   = (const float*)d_in[0];
    const void*  ei  = d_in[1];
    const float* W1  = (const float*)d_in[2];
    const float* b1  = (const float*)d_in[3];
    const float* W2  = (const float*)d_in[4];
    const float* b2  = (const float*)d_in[5];
    float*       out = (float*)d_out;

    int N = in_sizes[0] / D_IN; if (N > N_NODES) N = N_NODES;
    int E = in_sizes[1] / 2;    if (E > MAX_E)   E = MAX_E;
    const int T = 256;

    k_init<<<(N + T - 1) / T, T>>>(ei, N);
    k_convert<<<(E + T - 1) / T, T>>>(ei, E);   // E pairs of elements
    k_scan<<<NLB, T>>>(N);

    int fb = (E + T - 1) / T;              // fill blocks
    int gb = (N + 63) / 64;                // gemm1 blocks
    k_fill_gemm1<<<fb + gb, T>>>(E, x, W1, N, fb);

    k_gather1<<<(N + 31) / 32, T>>>(b1, N);
    k_gemm2<<<(N + 63) / 64, T>>>(W2, N);
    k_gather2<<<(N + 31) / 32, T>>>(b2, N);

    k_logits<<<(E + T - 1) / T, T>>>(out, E);
}